// round 13
// baseline (speedup 1.0000x reference)
#include <cuda_runtime.h>
#include <cstdint>
#include <cstddef>

#define NC 10
#define DD 512
#define D4 128          // DD/4
#define SEG_BLOCKS 296
#define SEG_GROUPS (SEG_BLOCKS * 4)
#define SEG_SMEM (4 * NC * D4 * 16)   // 81920 bytes
#define LOG_GRID 740                  // 5 blocks/SM x 148: one co-resident wave

typedef unsigned long long ull;

// Scratch (no cudaMalloc allowed)
__device__ float  g_sums[NC * DD];
__device__ int    g_counts[NC];
__device__ float4 g_proto4[NC * D4];
__device__ float  g_sqp[NC];
__device__ float  g_loss;

static __device__ __forceinline__ ull fma2(ull a, ull b, ull c) {
    ull d;
    asm("fma.rn.f32x2 %0, %1, %2, %3;" : "=l"(d) : "l"(a), "l"(b), "l"(c));
    return d;
}
static __device__ __forceinline__ float u64_sum2(ull v) {
    float lo, hi;
    asm("mov.b64 {%0,%1}, %2;" : "=f"(lo), "=f"(hi) : "l"(v));
    return lo + hi;
}

// ---------------------------------------------------------------------------
// K0: zero atomic accumulators (fresh every graph replay).
// ---------------------------------------------------------------------------
__global__ void k_zero() {
    int i = blockIdx.x * blockDim.x + threadIdx.x;
    if (i < NC * DD) g_sums[i] = 0.0f;
    if (i < NC)      g_counts[i] = 0;
    if (i == 0)      g_loss = 0.0f;
}

// ---------------------------------------------------------------------------
// K1: segment sums: 4 smem replicas + depth-1 prefetch (~5.6 TB/s), direct
// atomicAdd flush (no partials kernel). Streams E forward -> tail of E stays
// L2-resident for tail-first k_logits; k_logits ends at head, feeding the
// NEXT replay's segsum (strided sweep starts at rows [0,4736)).
// ---------------------------------------------------------------------------
__global__ __launch_bounds__(512) void k_segsum(const float4* __restrict__ E4,
                                                const int* __restrict__ labels,
                                                int nrows) {
    extern __shared__ float4 sm4[];            // [4][NC][D4]
    __shared__ int scnt[NC];
    const int g = threadIdx.x >> 7;
    const int t = threadIdx.x & 127;
    float4* rep = sm4 + g * (NC * D4);

    if (threadIdx.x < NC) scnt[threadIdx.x] = 0;
#pragma unroll
    for (int c = 0; c < NC; c++) rep[c * D4 + t] = make_float4(0.f, 0.f, 0.f, 0.f);
    __syncthreads();

    const int  gid    = blockIdx.x * 4 + g;
    const long stride = (long)SEG_GROUPS * 4;
    long r = (long)gid * 4;

    int4  lab = make_int4(0, 0, 0, 0);
    float4 v0, v1, v2, v3;
    bool have = (r + 4 <= nrows);
    if (have) {
        lab = *(const int4*)(labels + r);
        v0 = E4[(size_t)(r + 0) * D4 + t];
        v1 = E4[(size_t)(r + 1) * D4 + t];
        v2 = E4[(size_t)(r + 2) * D4 + t];
        v3 = E4[(size_t)(r + 3) * D4 + t];
    }
    while (have) {
        const long rn   = r + stride;
        const bool haven = (rn + 4 <= nrows);
        int4  labn = lab;
        float4 n0 = v0, n1 = v1, n2 = v2, n3 = v3;
        if (haven) {
            labn = *(const int4*)(labels + rn);
            n0 = E4[(size_t)(rn + 0) * D4 + t];
            n1 = E4[(size_t)(rn + 1) * D4 + t];
            n2 = E4[(size_t)(rn + 2) * D4 + t];
            n3 = E4[(size_t)(rn + 3) * D4 + t];
        }
        if (t == 0) {
            atomicAdd(&scnt[lab.x], 1); atomicAdd(&scnt[lab.y], 1);
            atomicAdd(&scnt[lab.z], 1); atomicAdd(&scnt[lab.w], 1);
        }
        float4* p;
        p = &rep[lab.x * D4 + t];
        { float4 a = *p; a.x += v0.x; a.y += v0.y; a.z += v0.z; a.w += v0.w; *p = a; }
        p = &rep[lab.y * D4 + t];
        { float4 a = *p; a.x += v1.x; a.y += v1.y; a.z += v1.z; a.w += v1.w; *p = a; }
        p = &rep[lab.z * D4 + t];
        { float4 a = *p; a.x += v2.x; a.y += v2.y; a.z += v2.z; a.w += v2.w; *p = a; }
        p = &rep[lab.w * D4 + t];
        { float4 a = *p; a.x += v3.x; a.y += v3.y; a.z += v3.z; a.w += v3.w; *p = a; }
        r = rn; have = haven;
        lab = labn; v0 = n0; v1 = n1; v2 = n2; v3 = n3;
    }
    if (r < nrows) {
        for (long rr = r; rr < nrows && rr < r + 4; rr++) {
            int lj = labels[rr];
            float4 v = E4[(size_t)rr * D4 + t];
            if (t == 0) atomicAdd(&scnt[lj], 1);
            float4* p = &rep[lj * D4 + t];
            float4 a = *p; a.x += v.x; a.y += v.y; a.z += v.z; a.w += v.w; *p = a;
        }
    }
    __syncthreads();

    // Reduce the 4 replicas and flush straight to global atomics.
    for (int i = threadIdx.x; i < NC * D4; i += 512) {
        float4 a = sm4[i];
        float4 b = sm4[NC * D4 + i];
        float4 c = sm4[2 * NC * D4 + i];
        float4 d = sm4[3 * NC * D4 + i];
        a.x += b.x + c.x + d.x;
        a.y += b.y + c.y + d.y;
        a.z += b.z + c.z + d.z;
        a.w += b.w + c.w + d.w;
        atomicAdd(&g_sums[i * 4 + 0], a.x);
        atomicAdd(&g_sums[i * 4 + 1], a.y);
        atomicAdd(&g_sums[i * 4 + 2], a.z);
        atomicAdd(&g_sums[i * 4 + 3], a.w);
    }
    if (threadIdx.x < NC && scnt[threadIdx.x])
        atomicAdd(&g_counts[threadIdx.x], scnt[threadIdx.x]);
}

// ---------------------------------------------------------------------------
// K3: prototypes = sums / counts ; sq_p[c] = ||p_c||^2.
// ---------------------------------------------------------------------------
__global__ __launch_bounds__(512) void k_proto() {
    __shared__ float sinv[NC];
    const int tid = threadIdx.x, lane = tid & 31, w = tid >> 5;
    if (tid < NC) sinv[tid] = 1.0f / (float)g_counts[tid];
    __syncthreads();
    float* gp = (float*)g_proto4;
#pragma unroll
    for (int c = 0; c < NC; c++) gp[c * DD + tid] = g_sums[c * DD + tid] * sinv[c];
    __syncthreads();
    if (w < NC) {
        const float* p = gp + w * DD;
        float acc = 0.f;
        for (int j = lane; j < DD; j += 32) acc = fmaf(p[j], p[j], acc);
#pragma unroll
        for (int st = 16; st >= 1; st >>= 1) acc += __shfl_xor_sync(0xFFFFFFFFu, acc, st);
        if (lane == 0) g_sqp[w] = acc;
    }
}

// ---------------------------------------------------------------------------
// K4: logits + log-softmax + loss. R6 mainloop (best measured 84us family
// optimum), PERSISTENT: 740 blocks (one co-resident wave) each processing up
// to ceil(ntiles/740) tiles TAIL-FIRST. Saves 1308 block prologues (20KB
// proto reload each) and wave transitions; preserves the L2 handoff in both
// directions (starts at tail where segsum ended; ends at head where the next
// replay's segsum starts).
// Lane layout per warp: lane = g*8 + ch*4 + dimq; group g owns 4 rows.
// ---------------------------------------------------------------------------
__global__ __launch_bounds__(128, 5) void k_logits(const float4* __restrict__ E4,
                                                   const int* __restrict__ labels,
                                                   float* __restrict__ out,
                                                   int nrows) {
    __shared__ float4 sp[NC * D4];   // 20 KB prototypes
    __shared__ float  ssqp[NC];
    __shared__ float  sloss;

    for (int i = threadIdx.x; i < NC * D4; i += 128) sp[i] = g_proto4[i];
    if (threadIdx.x < NC) ssqp[threadIdx.x] = g_sqp[threadIdx.x];
    if (threadIdx.x == 0) sloss = 0.f;
    __syncthreads();

    const int warp = threadIdx.x >> 5;
    const int lane = threadIdx.x & 31;
    const int dimq = lane & 3;
    const int ch   = (lane >> 2) & 1;
    const int g    = lane >> 3;
    const unsigned gmask = 0xFFu << (g * 8);

    const int ntiles = (nrows + 63) / 64;
    const ulonglong2* __restrict__ Pc =
        (const ulonglong2*)sp + (size_t)(ch * 5) * D4;

    float lvsum = 0.f;

    for (int w = 0; ; w++) {
        const int tile = ntiles - 1 - ((int)blockIdx.x + w * LOG_GRID);
        if (tile < 0) break;                       // block-uniform: shuffle-safe
        const int r0 = tile * 64 + warp * 16 + g * 4;

        int  rowc[4];
        bool valid[4];
#pragma unroll
        for (int j = 0; j < 4; j++) {
            int r = r0 + j;
            valid[j] = (r < nrows);
            rowc[j]  = valid[j] ? r : (nrows - 1);
        }

        const ulonglong2* __restrict__ Ep0 = (const ulonglong2*)E4 + (size_t)rowc[0] * D4;
        const ulonglong2* __restrict__ Ep1 = (const ulonglong2*)E4 + (size_t)rowc[1] * D4;
        const ulonglong2* __restrict__ Ep2 = (const ulonglong2*)E4 + (size_t)rowc[2] * D4;
        const ulonglong2* __restrict__ Ep3 = (const ulonglong2*)E4 + (size_t)rowc[3] * D4;

        ull dot[4][5];
#pragma unroll
        for (int j = 0; j < 4; j++)
#pragma unroll
            for (int c = 0; c < 5; c++) dot[j][c] = 0ull;
        ull sq[4] = {0ull, 0ull, 0ull, 0ull};

#pragma unroll 2
        for (int k = 0; k < 32; k++) {
            const int idx = k * 4 + dimq;
            ulonglong2 v0 = Ep0[idx];
            ulonglong2 v1 = Ep1[idx];
            ulonglong2 v2 = Ep2[idx];
            ulonglong2 v3 = Ep3[idx];
            sq[0] = fma2(v0.x, v0.x, sq[0]); sq[0] = fma2(v0.y, v0.y, sq[0]);
            sq[1] = fma2(v1.x, v1.x, sq[1]); sq[1] = fma2(v1.y, v1.y, sq[1]);
            sq[2] = fma2(v2.x, v2.x, sq[2]); sq[2] = fma2(v2.y, v2.y, sq[2]);
            sq[3] = fma2(v3.x, v3.x, sq[3]); sq[3] = fma2(v3.y, v3.y, sq[3]);
#pragma unroll
            for (int c = 0; c < 5; c++) {
                ulonglong2 p = Pc[c * D4 + idx];
                dot[0][c] = fma2(v0.x, p.x, dot[0][c]); dot[0][c] = fma2(v0.y, p.y, dot[0][c]);
                dot[1][c] = fma2(v1.x, p.x, dot[1][c]); dot[1][c] = fma2(v1.y, p.y, dot[1][c]);
                dot[2][c] = fma2(v2.x, p.x, dot[2][c]); dot[2][c] = fma2(v2.y, p.y, dot[2][c]);
                dot[3][c] = fma2(v3.x, p.x, dot[3][c]); dot[3][c] = fma2(v3.y, p.y, dot[3][c]);
            }
        }

#pragma unroll
        for (int j = 0; j < 4; j++) {
            float sqe = u64_sum2(sq[j]);
            sqe += __shfl_xor_sync(gmask, sqe, 1);
            sqe += __shfl_xor_sync(gmask, sqe, 2);

            float l[5];
            float m5 = -1e30f;
#pragma unroll
            for (int c = 0; c < 5; c++) {
                float d = u64_sum2(dot[j][c]);
                d += __shfl_xor_sync(gmask, d, 1);
                d += __shfl_xor_sync(gmask, d, 2);
                float d2 = sqe + ssqp[ch * 5 + c] - 2.0f * d;
                float lg = -fmaxf(d2, 0.0f);
                l[c] = lg;
                m5 = fmaxf(m5, lg);
            }
            float m = fmaxf(m5, __shfl_xor_sync(gmask, m5, 4));
            float se5 = 0.f;
#pragma unroll
            for (int c = 0; c < 5; c++) se5 += __expf(l[c] - m);
            float se = se5 + __shfl_xor_sync(gmask, se5, 4);

            const int lab = labels[rowc[j]];
            float lsel5 = 0.f;
#pragma unroll
            for (int c = 0; c < 5; c++)
                if (ch * 5 + c == lab) lsel5 = l[c];
            float lsel = lsel5 + __shfl_xor_sync(gmask, lsel5, 4);

            if (dimq == 0 && valid[j]) {
                float* o = out + 1 + (size_t)rowc[j] * NC + ch * 5;
#pragma unroll
                for (int c = 0; c < 5; c++) o[c] = l[c];
            }
            if (dimq == 0 && ch == 0 && valid[j])
                lvsum += m + __logf(se) - lsel;
        }
    }

    // Reconverged: full-warp reduce, then one global atomic per block.
#pragma unroll
    for (int st = 16; st >= 1; st >>= 1)
        lvsum += __shfl_xor_sync(0xFFFFFFFFu, lvsum, st);
    if (lane == 0) atomicAdd(&sloss, lvsum);
    __syncthreads();
    if (threadIdx.x == 0) atomicAdd(&g_loss, sloss);
}

// ---------------------------------------------------------------------------
// K5: finalize loss
// ---------------------------------------------------------------------------
__global__ void k_final(float* __restrict__ out, int nrows) {
    out[0] = g_loss * (1.0f / (float)nrows);
}

extern "C" void kernel_launch(void* const* d_in, const int* in_sizes, int n_in,
                              void* d_out, int out_size) {
    const float* E      = (const float*)d_in[0];
    const int*   labels = (const int*)d_in[1];
    float*       out    = (float*)d_out;
    const int nrows = in_sizes[1];   // 131072

    cudaFuncSetAttribute(k_segsum, cudaFuncAttributeMaxDynamicSharedMemorySize,
                         SEG_SMEM);

    k_zero<<<20, 256>>>();
    k_segsum<<<SEG_BLOCKS, 512, SEG_SMEM>>>((const float4*)E, labels, nrows);
    k_proto<<<1, 512>>>();
    k_logits<<<LOG_GRID, 128>>>((const float4*)E, labels, out, nrows);
    k_final<<<1, 1>>>(out, nrows);
}

// round 14
// speedup vs baseline: 1.0311x; 1.0311x over previous
#include <cuda_runtime.h>
#include <cstdint>
#include <cstddef>

#define NC 10
#define DD 512
#define D4 128          // DD/4
#define SEG_BLOCKS 296
#define SEG_GROUPS (SEG_BLOCKS * 4)
#define SEG_SMEM (4 * NC * D4 * 16)   // 81920 bytes

typedef unsigned long long ull;

// Scratch (no cudaMalloc allowed)
__device__ float4 g_part4[SEG_BLOCKS * NC * D4];   // 6.06 MB partial sums
__device__ int    g_cnt_part[SEG_BLOCKS * NC];
__device__ float4 g_sums4[NC * D4];
__device__ float4 g_proto4[NC * D4];
__device__ float  g_sqp[NC];
__device__ float  g_loss;

static __device__ __forceinline__ ull fma2(ull a, ull b, ull c) {
    ull d;
    asm("fma.rn.f32x2 %0, %1, %2, %3;" : "=l"(d) : "l"(a), "l"(b), "l"(c));
    return d;
}
static __device__ __forceinline__ float u64_sum2(ull v) {
    float lo, hi;
    asm("mov.b64 {%0,%1}, %2;" : "=f"(lo), "=f"(hi) : "l"(v));
    return lo + hi;
}

// ---------------------------------------------------------------------------
// K1: segment sums (R12 form: 4 replicas + depth-1 prefetch, partials flush).
// Streams E FORWARD -> tail of E stays L2-resident for reversed k_logits.
// ---------------------------------------------------------------------------
__global__ __launch_bounds__(512) void k_segsum(const float4* __restrict__ E4,
                                                const int* __restrict__ labels,
                                                int nrows) {
    extern __shared__ float4 sm4[];            // [4][NC][D4]
    __shared__ int scnt[NC];
    const int g = threadIdx.x >> 7;
    const int t = threadIdx.x & 127;
    float4* rep = sm4 + g * (NC * D4);

    if (threadIdx.x < NC) scnt[threadIdx.x] = 0;
#pragma unroll
    for (int c = 0; c < NC; c++) rep[c * D4 + t] = make_float4(0.f, 0.f, 0.f, 0.f);
    __syncthreads();

    const int  gid    = blockIdx.x * 4 + g;
    const long stride = (long)SEG_GROUPS * 4;
    long r = (long)gid * 4;

    int4  lab = make_int4(0, 0, 0, 0);
    float4 v0, v1, v2, v3;
    bool have = (r + 4 <= nrows);
    if (have) {
        lab = *(const int4*)(labels + r);
        v0 = E4[(size_t)(r + 0) * D4 + t];
        v1 = E4[(size_t)(r + 1) * D4 + t];
        v2 = E4[(size_t)(r + 2) * D4 + t];
        v3 = E4[(size_t)(r + 3) * D4 + t];
    }
    while (have) {
        const long rn   = r + stride;
        const bool haven = (rn + 4 <= nrows);
        int4  labn = lab;
        float4 n0 = v0, n1 = v1, n2 = v2, n3 = v3;
        if (haven) {
            labn = *(const int4*)(labels + rn);
            n0 = E4[(size_t)(rn + 0) * D4 + t];
            n1 = E4[(size_t)(rn + 1) * D4 + t];
            n2 = E4[(size_t)(rn + 2) * D4 + t];
            n3 = E4[(size_t)(rn + 3) * D4 + t];
        }
        if (t == 0) {
            atomicAdd(&scnt[lab.x], 1); atomicAdd(&scnt[lab.y], 1);
            atomicAdd(&scnt[lab.z], 1); atomicAdd(&scnt[lab.w], 1);
        }
        float4* p;
        p = &rep[lab.x * D4 + t];
        { float4 a = *p; a.x += v0.x; a.y += v0.y; a.z += v0.z; a.w += v0.w; *p = a; }
        p = &rep[lab.y * D4 + t];
        { float4 a = *p; a.x += v1.x; a.y += v1.y; a.z += v1.z; a.w += v1.w; *p = a; }
        p = &rep[lab.z * D4 + t];
        { float4 a = *p; a.x += v2.x; a.y += v2.y; a.z += v2.z; a.w += v2.w; *p = a; }
        p = &rep[lab.w * D4 + t];
        { float4 a = *p; a.x += v3.x; a.y += v3.y; a.z += v3.z; a.w += v3.w; *p = a; }
        r = rn; have = haven;
        lab = labn; v0 = n0; v1 = n1; v2 = n2; v3 = n3;
    }
    if (r < nrows) {
        for (long rr = r; rr < nrows && rr < r + 4; rr++) {
            int lj = labels[rr];
            float4 v = E4[(size_t)rr * D4 + t];
            if (t == 0) atomicAdd(&scnt[lj], 1);
            float4* p = &rep[lj * D4 + t];
            float4 a = *p; a.x += v.x; a.y += v.y; a.z += v.z; a.w += v.w; *p = a;
        }
    }
    __syncthreads();

    for (int i = threadIdx.x; i < NC * D4; i += 512) {
        float4 a = sm4[i];
        float4 b = sm4[NC * D4 + i];
        float4 c = sm4[2 * NC * D4 + i];
        float4 d = sm4[3 * NC * D4 + i];
        a.x += b.x + c.x + d.x;
        a.y += b.y + c.y + d.y;
        a.z += b.z + c.z + d.z;
        a.w += b.w + c.w + d.w;
        g_part4[blockIdx.x * (NC * D4) + i] = a;
    }
    if (threadIdx.x < NC)
        g_cnt_part[blockIdx.x * NC + threadIdx.x] = scnt[threadIdx.x];
}

// ---------------------------------------------------------------------------
// K2: reduce partials -> g_sums4. grid 80 x 128: 8 threads per f4 element.
// ---------------------------------------------------------------------------
__global__ __launch_bounds__(128) void k_reduce() {
    const int i  = blockIdx.x * 16 + (threadIdx.x >> 3);   // f4 element 0..1279
    const int ps = threadIdx.x & 7;
    float4 acc = make_float4(0.f, 0.f, 0.f, 0.f);
#pragma unroll 4
    for (int p = ps; p < SEG_BLOCKS; p += 8) {
        float4 v = g_part4[p * (NC * D4) + i];
        acc.x += v.x; acc.y += v.y; acc.z += v.z; acc.w += v.w;
    }
#pragma unroll
    for (int st = 1; st <= 4; st <<= 1) {
        acc.x += __shfl_xor_sync(0xFFFFFFFFu, acc.x, st);
        acc.y += __shfl_xor_sync(0xFFFFFFFFu, acc.y, st);
        acc.z += __shfl_xor_sync(0xFFFFFFFFu, acc.z, st);
        acc.w += __shfl_xor_sync(0xFFFFFFFFu, acc.w, st);
    }
    if (ps == 0) g_sums4[i] = acc;
}

// ---------------------------------------------------------------------------
// K3: counts -> prototypes -> ||p||^2 ; zero g_loss.
// ---------------------------------------------------------------------------
__global__ __launch_bounds__(512) void k_proto() {
    __shared__ float sinv[NC];
    const int tid = threadIdx.x, lane = tid & 31, w = tid >> 5;
    if (w < NC) {
        int s = 0;
        for (int p = lane; p < SEG_BLOCKS; p += 32) s += g_cnt_part[p * NC + w];
#pragma unroll
        for (int st = 16; st >= 1; st >>= 1) s += __shfl_xor_sync(0xFFFFFFFFu, s, st);
        if (lane == 0) sinv[w] = 1.0f / (float)s;
    }
    if (tid == 0) g_loss = 0.f;
    __syncthreads();
    const float* gs = (const float*)g_sums4;
    float*       gp = (float*)g_proto4;
#pragma unroll
    for (int c = 0; c < NC; c++) gp[c * DD + tid] = gs[c * DD + tid] * sinv[c];
    __syncthreads();
    if (w < NC) {
        const float* p = gp + w * DD;
        float acc = 0.f;
        for (int j = lane; j < DD; j += 32) acc = fmaf(p[j], p[j], acc);
#pragma unroll
        for (int st = 16; st >= 1; st >>= 1) acc += __shfl_xor_sync(0xFFFFFFFFu, acc, st);
        if (lane == 0) g_sqp[w] = acc;
    }
}

// ---------------------------------------------------------------------------
// K4: logits + log-softmax + loss. EXACT R12 kernel (measured 84.0us) with
// reversed block->row mapping (cross-replay L2 handoff) and int4 label loads.
// Lane layout per warp: lane = g*8 + ch*4 + dimq; group g owns 4 rows.
// ---------------------------------------------------------------------------
__global__ __launch_bounds__(128, 5) void k_logits(const float4* __restrict__ E4,
                                                   const int* __restrict__ labels,
                                                   float* __restrict__ out,
                                                   int nrows) {
    __shared__ float4 sp[NC * D4];   // 20 KB prototypes
    __shared__ float  ssqp[NC];
    __shared__ float  sloss;

    for (int i = threadIdx.x; i < NC * D4; i += 128) sp[i] = g_proto4[i];
    if (threadIdx.x < NC) ssqp[threadIdx.x] = g_sqp[threadIdx.x];
    if (threadIdx.x == 0) sloss = 0.f;
    __syncthreads();

    const int warp = threadIdx.x >> 5;
    const int lane = threadIdx.x & 31;
    const int dimq = lane & 3;
    const int ch   = (lane >> 2) & 1;
    const int g    = lane >> 3;
    const unsigned gmask = 0xFFu << (g * 8);
    // Reversed mapping: early blocks (scheduled first) take the LAST rows.
    const int rblk = (int)gridDim.x - 1 - (int)blockIdx.x;
    const int r0   = rblk * 64 + warp * 16 + g * 4;

    // Clamped row indices: loads always in-bounds, stores gated by valid.
    int  rowc[4];
    bool valid[4];
#pragma unroll
    for (int j = 0; j < 4; j++) {
        int r = r0 + j;
        valid[j] = (r < nrows);
        rowc[j]  = valid[j] ? r : (nrows - 1);
    }
    // Vectorized label load on the (overwhelmingly common) full-tile path.
    // The branch contains no shuffles -> divergence-safe.
    int lab4[4];
    if (r0 + 4 <= nrows) {
        const int4 lv = *(const int4*)(labels + r0);
        lab4[0] = lv.x; lab4[1] = lv.y; lab4[2] = lv.z; lab4[3] = lv.w;
    } else {
#pragma unroll
        for (int j = 0; j < 4; j++) lab4[j] = labels[rowc[j]];
    }

    const ulonglong2* __restrict__ Pp  = (const ulonglong2*)sp;
    const ulonglong2* __restrict__ Ep0 = (const ulonglong2*)E4 + (size_t)rowc[0] * D4;
    const ulonglong2* __restrict__ Ep1 = (const ulonglong2*)E4 + (size_t)rowc[1] * D4;
    const ulonglong2* __restrict__ Ep2 = (const ulonglong2*)E4 + (size_t)rowc[2] * D4;
    const ulonglong2* __restrict__ Ep3 = (const ulonglong2*)E4 + (size_t)rowc[3] * D4;
    const ulonglong2* __restrict__ Pc  = Pp + (size_t)(ch * 5) * D4;

    ull dot[4][5];
#pragma unroll
    for (int j = 0; j < 4; j++)
#pragma unroll
        for (int c = 0; c < 5; c++) dot[j][c] = 0ull;
    ull sq[4] = {0ull, 0ull, 0ull, 0ull};

#pragma unroll 2
    for (int k = 0; k < 32; k++) {
        const int idx = k * 4 + dimq;
        ulonglong2 v0 = Ep0[idx];
        ulonglong2 v1 = Ep1[idx];
        ulonglong2 v2 = Ep2[idx];
        ulonglong2 v3 = Ep3[idx];
        sq[0] = fma2(v0.x, v0.x, sq[0]); sq[0] = fma2(v0.y, v0.y, sq[0]);
        sq[1] = fma2(v1.x, v1.x, sq[1]); sq[1] = fma2(v1.y, v1.y, sq[1]);
        sq[2] = fma2(v2.x, v2.x, sq[2]); sq[2] = fma2(v2.y, v2.y, sq[2]);
        sq[3] = fma2(v3.x, v3.x, sq[3]); sq[3] = fma2(v3.y, v3.y, sq[3]);
#pragma unroll
        for (int c = 0; c < 5; c++) {
            ulonglong2 p = Pc[c * D4 + idx];
            dot[0][c] = fma2(v0.x, p.x, dot[0][c]); dot[0][c] = fma2(v0.y, p.y, dot[0][c]);
            dot[1][c] = fma2(v1.x, p.x, dot[1][c]); dot[1][c] = fma2(v1.y, p.y, dot[1][c]);
            dot[2][c] = fma2(v2.x, p.x, dot[2][c]); dot[2][c] = fma2(v2.y, p.y, dot[2][c]);
            dot[3][c] = fma2(v3.x, p.x, dot[3][c]); dot[3][c] = fma2(v3.y, p.y, dot[3][c]);
        }
    }

    float lvsum = 0.f;
#pragma unroll
    for (int j = 0; j < 4; j++) {
        float sqe = u64_sum2(sq[j]);
        sqe += __shfl_xor_sync(gmask, sqe, 1);
        sqe += __shfl_xor_sync(gmask, sqe, 2);

        float l[5];
        float m5 = -1e30f;
#pragma unroll
        for (int c = 0; c < 5; c++) {
            float d = u64_sum2(dot[j][c]);
            d += __shfl_xor_sync(gmask, d, 1);
            d += __shfl_xor_sync(gmask, d, 2);
            float d2 = sqe + ssqp[ch * 5 + c] - 2.0f * d;
            float lg = -fmaxf(d2, 0.0f);
            l[c] = lg;
            m5 = fmaxf(m5, lg);
        }
        float m = fmaxf(m5, __shfl_xor_sync(gmask, m5, 4));
        float se5 = 0.f;
#pragma unroll
        for (int c = 0; c < 5; c++) se5 += __expf(l[c] - m);
        float se = se5 + __shfl_xor_sync(gmask, se5, 4);

        const int lab = lab4[j];
        float lsel5 = 0.f;
#pragma unroll
        for (int c = 0; c < 5; c++)
            if (ch * 5 + c == lab) lsel5 = l[c];
        float lsel = lsel5 + __shfl_xor_sync(gmask, lsel5, 4);

        if (dimq == 0 && valid[j]) {
            float* o = out + 1 + (size_t)rowc[j] * NC + ch * 5;
#pragma unroll
            for (int c = 0; c < 5; c++) o[c] = l[c];
        }
        if (dimq == 0 && ch == 0 && valid[j])
            lvsum += m + __logf(se) - lsel;
    }

#pragma unroll
    for (int st = 16; st >= 1; st >>= 1)
        lvsum += __shfl_xor_sync(0xFFFFFFFFu, lvsum, st);
    if (lane == 0) atomicAdd(&sloss, lvsum);
    __syncthreads();
    if (threadIdx.x == 0) atomicAdd(&g_loss, sloss);
}

// ---------------------------------------------------------------------------
// K5: finalize loss
// ---------------------------------------------------------------------------
__global__ void k_final(float* __restrict__ out, int nrows) {
    out[0] = g_loss * (1.0f / (float)nrows);
}

extern "C" void kernel_launch(void* const* d_in, const int* in_sizes, int n_in,
                              void* d_out, int out_size) {
    const float* E      = (const float*)d_in[0];
    const int*   labels = (const int*)d_in[1];
    float*       out    = (float*)d_out;
    const int nrows = in_sizes[1];   // 131072

    cudaFuncSetAttribute(k_segsum, cudaFuncAttributeMaxDynamicSharedMemorySize,
                         SEG_SMEM);

    k_segsum<<<SEG_BLOCKS, 512, SEG_SMEM>>>((const float4*)E, labels, nrows);
    k_reduce<<<80, 128>>>();
    k_proto<<<1, 512>>>();
    k_logits<<<(nrows + 63) / 64, 128>>>((const float4*)E, labels, out, nrows);
    k_final<<<1, 1>>>(out, nrows);
}

// round 15
// speedup vs baseline: 1.0649x; 1.0328x over previous
#include <cuda_runtime.h>
#include <cstdint>
#include <cstddef>

#define NC 10
#define DD 512
#define D4 128          // DD/4
#define SEG_BLOCKS 296
#define SEG_GROUPS (SEG_BLOCKS * 4)
#define SEG_SMEM (4 * NC * D4 * 16)   // 81920 bytes

typedef unsigned long long ull;

// Scratch (no cudaMalloc allowed)
__device__ float4 g_part4[SEG_BLOCKS * NC * D4];   // 6.06 MB partial sums
__device__ int    g_cnt_part[SEG_BLOCKS * NC];
__device__ float4 g_sums4[NC * D4];
__device__ float4 g_proto4[NC * D4];
__device__ float  g_sqp[NC];
__device__ float  g_loss;

static __device__ __forceinline__ ull fma2(ull a, ull b, ull c) {
    ull d;
    asm("fma.rn.f32x2 %0, %1, %2, %3;" : "=l"(d) : "l"(a), "l"(b), "l"(c));
    return d;
}
static __device__ __forceinline__ float u64_sum2(ull v) {
    float lo, hi;
    asm("mov.b64 {%0,%1}, %2;" : "=f"(lo), "=f"(hi) : "l"(v));
    return lo + hi;
}

// ---------------------------------------------------------------------------
// K1: segment sums (R12/R14 form: 4 replicas + depth-1 prefetch, partials).
// Streams E FORWARD -> tail of E stays L2-resident for reversed k_logits.
// ---------------------------------------------------------------------------
__global__ __launch_bounds__(512) void k_segsum(const float4* __restrict__ E4,
                                                const int* __restrict__ labels,
                                                int nrows) {
    extern __shared__ float4 sm4[];            // [4][NC][D4]
    __shared__ int scnt[NC];
    const int g = threadIdx.x >> 7;
    const int t = threadIdx.x & 127;
    float4* rep = sm4 + g * (NC * D4);

    if (threadIdx.x < NC) scnt[threadIdx.x] = 0;
#pragma unroll
    for (int c = 0; c < NC; c++) rep[c * D4 + t] = make_float4(0.f, 0.f, 0.f, 0.f);
    __syncthreads();

    const int  gid    = blockIdx.x * 4 + g;
    const long stride = (long)SEG_GROUPS * 4;
    long r = (long)gid * 4;

    int4  lab = make_int4(0, 0, 0, 0);
    float4 v0, v1, v2, v3;
    bool have = (r + 4 <= nrows);
    if (have) {
        lab = *(const int4*)(labels + r);
        v0 = E4[(size_t)(r + 0) * D4 + t];
        v1 = E4[(size_t)(r + 1) * D4 + t];
        v2 = E4[(size_t)(r + 2) * D4 + t];
        v3 = E4[(size_t)(r + 3) * D4 + t];
    }
    while (have) {
        const long rn   = r + stride;
        const bool haven = (rn + 4 <= nrows);
        int4  labn = lab;
        float4 n0 = v0, n1 = v1, n2 = v2, n3 = v3;
        if (haven) {
            labn = *(const int4*)(labels + rn);
            n0 = E4[(size_t)(rn + 0) * D4 + t];
            n1 = E4[(size_t)(rn + 1) * D4 + t];
            n2 = E4[(size_t)(rn + 2) * D4 + t];
            n3 = E4[(size_t)(rn + 3) * D4 + t];
        }
        if (t == 0) {
            atomicAdd(&scnt[lab.x], 1); atomicAdd(&scnt[lab.y], 1);
            atomicAdd(&scnt[lab.z], 1); atomicAdd(&scnt[lab.w], 1);
        }
        float4* p;
        p = &rep[lab.x * D4 + t];
        { float4 a = *p; a.x += v0.x; a.y += v0.y; a.z += v0.z; a.w += v0.w; *p = a; }
        p = &rep[lab.y * D4 + t];
        { float4 a = *p; a.x += v1.x; a.y += v1.y; a.z += v1.z; a.w += v1.w; *p = a; }
        p = &rep[lab.z * D4 + t];
        { float4 a = *p; a.x += v2.x; a.y += v2.y; a.z += v2.z; a.w += v2.w; *p = a; }
        p = &rep[lab.w * D4 + t];
        { float4 a = *p; a.x += v3.x; a.y += v3.y; a.z += v3.z; a.w += v3.w; *p = a; }
        r = rn; have = haven;
        lab = labn; v0 = n0; v1 = n1; v2 = n2; v3 = n3;
    }
    if (r < nrows) {
        for (long rr = r; rr < nrows && rr < r + 4; rr++) {
            int lj = labels[rr];
            float4 v = E4[(size_t)rr * D4 + t];
            if (t == 0) atomicAdd(&scnt[lj], 1);
            float4* p = &rep[lj * D4 + t];
            float4 a = *p; a.x += v.x; a.y += v.y; a.z += v.z; a.w += v.w; *p = a;
        }
    }
    __syncthreads();

    for (int i = threadIdx.x; i < NC * D4; i += 512) {
        float4 a = sm4[i];
        float4 b = sm4[NC * D4 + i];
        float4 c = sm4[2 * NC * D4 + i];
        float4 d = sm4[3 * NC * D4 + i];
        a.x += b.x + c.x + d.x;
        a.y += b.y + c.y + d.y;
        a.z += b.z + c.z + d.z;
        a.w += b.w + c.w + d.w;
        g_part4[blockIdx.x * (NC * D4) + i] = a;
    }
    if (threadIdx.x < NC)
        g_cnt_part[blockIdx.x * NC + threadIdx.x] = scnt[threadIdx.x];
}

// ---------------------------------------------------------------------------
// K2: reduce partials -> g_sums4. grid 80 x 128 (R14 measured-better form).
// ---------------------------------------------------------------------------
__global__ __launch_bounds__(128) void k_reduce() {
    const int i  = blockIdx.x * 16 + (threadIdx.x >> 3);   // f4 element 0..1279
    const int ps = threadIdx.x & 7;
    float4 acc = make_float4(0.f, 0.f, 0.f, 0.f);
#pragma unroll 4
    for (int p = ps; p < SEG_BLOCKS; p += 8) {
        float4 v = g_part4[p * (NC * D4) + i];
        acc.x += v.x; acc.y += v.y; acc.z += v.z; acc.w += v.w;
    }
#pragma unroll
    for (int st = 1; st <= 4; st <<= 1) {
        acc.x += __shfl_xor_sync(0xFFFFFFFFu, acc.x, st);
        acc.y += __shfl_xor_sync(0xFFFFFFFFu, acc.y, st);
        acc.z += __shfl_xor_sync(0xFFFFFFFFu, acc.z, st);
        acc.w += __shfl_xor_sync(0xFFFFFFFFu, acc.w, st);
    }
    if (ps == 0) g_sums4[i] = acc;
}

// ---------------------------------------------------------------------------
// K3: counts -> prototypes -> ||p||^2 ; zero g_loss.
// ---------------------------------------------------------------------------
__global__ __launch_bounds__(512) void k_proto() {
    __shared__ float sinv[NC];
    const int tid = threadIdx.x, lane = tid & 31, w = tid >> 5;
    if (w < NC) {
        int s = 0;
        for (int p = lane; p < SEG_BLOCKS; p += 32) s += g_cnt_part[p * NC + w];
#pragma unroll
        for (int st = 16; st >= 1; st >>= 1) s += __shfl_xor_sync(0xFFFFFFFFu, s, st);
        if (lane == 0) sinv[w] = 1.0f / (float)s;
    }
    if (tid == 0) g_loss = 0.f;
    __syncthreads();
    const float* gs = (const float*)g_sums4;
    float*       gp = (float*)g_proto4;
#pragma unroll
    for (int c = 0; c < NC; c++) gp[c * DD + tid] = gs[c * DD + tid] * sinv[c];
    __syncthreads();
    if (w < NC) {
        const float* p = gp + w * DD;
        float acc = 0.f;
        for (int j = lane; j < DD; j += 32) acc = fmaf(p[j], p[j], acc);
#pragma unroll
        for (int st = 16; st >= 1; st >>= 1) acc += __shfl_xor_sync(0xFFFFFFFFu, acc, st);
        if (lane == 0) g_sqp[w] = acc;
    }
}

// ---------------------------------------------------------------------------
// K4: logits + log-softmax + loss. EXACT R12 kernel (measured 84.0us):
// reversed block->row mapping, labels loaded scalar in the epilogue (NOT
// hoisted — R14 showed hoisting regresses the schedule). FROZEN.
// Lane layout per warp: lane = g*8 + ch*4 + dimq; group g owns 4 rows.
// ---------------------------------------------------------------------------
__global__ __launch_bounds__(128, 5) void k_logits(const float4* __restrict__ E4,
                                                   const int* __restrict__ labels,
                                                   float* __restrict__ out,
                                                   int nrows) {
    __shared__ float4 sp[NC * D4];   // 20 KB prototypes
    __shared__ float  ssqp[NC];
    __shared__ float  sloss;

    for (int i = threadIdx.x; i < NC * D4; i += 128) sp[i] = g_proto4[i];
    if (threadIdx.x < NC) ssqp[threadIdx.x] = g_sqp[threadIdx.x];
    if (threadIdx.x == 0) sloss = 0.f;
    __syncthreads();

    const int warp = threadIdx.x >> 5;
    const int lane = threadIdx.x & 31;
    const int dimq = lane & 3;
    const int ch   = (lane >> 2) & 1;
    const int g    = lane >> 3;
    const unsigned gmask = 0xFFu << (g * 8);
    // Reversed mapping: early blocks (scheduled first) take the LAST rows.
    const int rblk = (int)gridDim.x - 1 - (int)blockIdx.x;
    const int r0   = rblk * 64 + warp * 16 + g * 4;

    // Clamped row indices: loads always in-bounds, stores gated by valid.
    int  rowc[4];
    bool valid[4];
#pragma unroll
    for (int j = 0; j < 4; j++) {
        int r = r0 + j;
        valid[j] = (r < nrows);
        rowc[j]  = valid[j] ? r : (nrows - 1);
    }

    const ulonglong2* __restrict__ Pp  = (const ulonglong2*)sp;
    const ulonglong2* __restrict__ Ep0 = (const ulonglong2*)E4 + (size_t)rowc[0] * D4;
    const ulonglong2* __restrict__ Ep1 = (const ulonglong2*)E4 + (size_t)rowc[1] * D4;
    const ulonglong2* __restrict__ Ep2 = (const ulonglong2*)E4 + (size_t)rowc[2] * D4;
    const ulonglong2* __restrict__ Ep3 = (const ulonglong2*)E4 + (size_t)rowc[3] * D4;
    const ulonglong2* __restrict__ Pc  = Pp + (size_t)(ch * 5) * D4;

    ull dot[4][5];
#pragma unroll
    for (int j = 0; j < 4; j++)
#pragma unroll
        for (int c = 0; c < 5; c++) dot[j][c] = 0ull;
    ull sq[4] = {0ull, 0ull, 0ull, 0ull};

#pragma unroll 2
    for (int k = 0; k < 32; k++) {
        const int idx = k * 4 + dimq;
        ulonglong2 v0 = Ep0[idx];
        ulonglong2 v1 = Ep1[idx];
        ulonglong2 v2 = Ep2[idx];
        ulonglong2 v3 = Ep3[idx];
        sq[0] = fma2(v0.x, v0.x, sq[0]); sq[0] = fma2(v0.y, v0.y, sq[0]);
        sq[1] = fma2(v1.x, v1.x, sq[1]); sq[1] = fma2(v1.y, v1.y, sq[1]);
        sq[2] = fma2(v2.x, v2.x, sq[2]); sq[2] = fma2(v2.y, v2.y, sq[2]);
        sq[3] = fma2(v3.x, v3.x, sq[3]); sq[3] = fma2(v3.y, v3.y, sq[3]);
#pragma unroll
        for (int c = 0; c < 5; c++) {
            ulonglong2 p = Pc[c * D4 + idx];
            dot[0][c] = fma2(v0.x, p.x, dot[0][c]); dot[0][c] = fma2(v0.y, p.y, dot[0][c]);
            dot[1][c] = fma2(v1.x, p.x, dot[1][c]); dot[1][c] = fma2(v1.y, p.y, dot[1][c]);
            dot[2][c] = fma2(v2.x, p.x, dot[2][c]); dot[2][c] = fma2(v2.y, p.y, dot[2][c]);
            dot[3][c] = fma2(v3.x, p.x, dot[3][c]); dot[3][c] = fma2(v3.y, p.y, dot[3][c]);
        }
    }

    float lvsum = 0.f;
#pragma unroll
    for (int j = 0; j < 4; j++) {
        float sqe = u64_sum2(sq[j]);
        sqe += __shfl_xor_sync(gmask, sqe, 1);
        sqe += __shfl_xor_sync(gmask, sqe, 2);

        float l[5];
        float m5 = -1e30f;
#pragma unroll
        for (int c = 0; c < 5; c++) {
            float d = u64_sum2(dot[j][c]);
            d += __shfl_xor_sync(gmask, d, 1);
            d += __shfl_xor_sync(gmask, d, 2);
            float d2 = sqe + ssqp[ch * 5 + c] - 2.0f * d;
            float lg = -fmaxf(d2, 0.0f);
            l[c] = lg;
            m5 = fmaxf(m5, lg);
        }
        float m = fmaxf(m5, __shfl_xor_sync(gmask, m5, 4));
        float se5 = 0.f;
#pragma unroll
        for (int c = 0; c < 5; c++) se5 += __expf(l[c] - m);
        float se = se5 + __shfl_xor_sync(gmask, se5, 4);

        const int lab = labels[rowc[j]];
        float lsel5 = 0.f;
#pragma unroll
        for (int c = 0; c < 5; c++)
            if (ch * 5 + c == lab) lsel5 = l[c];
        float lsel = lsel5 + __shfl_xor_sync(gmask, lsel5, 4);

        if (dimq == 0 && valid[j]) {
            float* o = out + 1 + (size_t)rowc[j] * NC + ch * 5;
#pragma unroll
            for (int c = 0; c < 5; c++) o[c] = l[c];
        }
        if (dimq == 0 && ch == 0 && valid[j])
            lvsum += m + __logf(se) - lsel;
    }

#pragma unroll
    for (int st = 16; st >= 1; st >>= 1)
        lvsum += __shfl_xor_sync(0xFFFFFFFFu, lvsum, st);
    if (lane == 0) atomicAdd(&sloss, lvsum);
    __syncthreads();
    if (threadIdx.x == 0) atomicAdd(&g_loss, sloss);
}

// ---------------------------------------------------------------------------
// K5: finalize loss
// ---------------------------------------------------------------------------
__global__ void k_final(float* __restrict__ out, int nrows) {
    out[0] = g_loss * (1.0f / (float)nrows);
}

extern "C" void kernel_launch(void* const* d_in, const int* in_sizes, int n_in,
                              void* d_out, int out_size) {
    const float* E      = (const float*)d_in[0];
    const int*   labels = (const int*)d_in[1];
    float*       out    = (float*)d_out;
    const int nrows = in_sizes[1];   // 131072

    cudaFuncSetAttribute(k_segsum, cudaFuncAttributeMaxDynamicSharedMemorySize,
                         SEG_SMEM);

    k_segsum<<<SEG_BLOCKS, 512, SEG_SMEM>>>((const float4*)E, labels, nrows);
    k_reduce<<<80, 128>>>();
    k_proto<<<1, 512>>>();
    k_logits<<<(nrows + 63) / 64, 128>>>((const float4*)E, labels, out, nrows);
    k_final<<<1, 1>>>(out, nrows);
}

// round 16
// speedup vs baseline: 1.1211x; 1.0527x over previous
#include <cuda_runtime.h>
#include <cstdint>
#include <cstddef>

#define NC 10
#define DD 512
#define D4 128          // DD/4
#define SEG_BLOCKS 296
#define SEG_GROUPS (SEG_BLOCKS * 4)
#define SEG_SMEM (4 * NC * D4 * 16)   // 81920 bytes

typedef unsigned long long ull;

// Scratch (no cudaMalloc allowed)
__device__ float4 g_part4[SEG_BLOCKS * NC * D4];   // 6.06 MB partial sums
__device__ int    g_cnt_part[SEG_BLOCKS * NC];
__device__ float4 g_proto4[NC * D4];
__device__ float  g_sqp_part[NC * 8];              // per-reduce-block ||p||^2 partials
__device__ float  g_loss;

static __device__ __forceinline__ ull fma2(ull a, ull b, ull c) {
    ull d;
    asm("fma.rn.f32x2 %0, %1, %2, %3;" : "=l"(d) : "l"(a), "l"(b), "l"(c));
    return d;
}
static __device__ __forceinline__ float u64_sum2(ull v) {
    float lo, hi;
    asm("mov.b64 {%0,%1}, %2;" : "=f"(lo), "=f"(hi) : "l"(v));
    return lo + hi;
}

// ---------------------------------------------------------------------------
// K1: segment sums (R15 form, unchanged: 4 replicas + depth-1 prefetch).
// Streams E FORWARD -> tail of E stays L2-resident for reversed k_logits.
// ---------------------------------------------------------------------------
__global__ __launch_bounds__(512) void k_segsum(const float4* __restrict__ E4,
                                                const int* __restrict__ labels,
                                                int nrows) {
    extern __shared__ float4 sm4[];            // [4][NC][D4]
    __shared__ int scnt[NC];
    const int g = threadIdx.x >> 7;
    const int t = threadIdx.x & 127;
    float4* rep = sm4 + g * (NC * D4);

    if (threadIdx.x < NC) scnt[threadIdx.x] = 0;
#pragma unroll
    for (int c = 0; c < NC; c++) rep[c * D4 + t] = make_float4(0.f, 0.f, 0.f, 0.f);
    __syncthreads();

    const int  gid    = blockIdx.x * 4 + g;
    const long stride = (long)SEG_GROUPS * 4;
    long r = (long)gid * 4;

    int4  lab = make_int4(0, 0, 0, 0);
    float4 v0, v1, v2, v3;
    bool have = (r + 4 <= nrows);
    if (have) {
        lab = *(const int4*)(labels + r);
        v0 = E4[(size_t)(r + 0) * D4 + t];
        v1 = E4[(size_t)(r + 1) * D4 + t];
        v2 = E4[(size_t)(r + 2) * D4 + t];
        v3 = E4[(size_t)(r + 3) * D4 + t];
    }
    while (have) {
        const long rn   = r + stride;
        const bool haven = (rn + 4 <= nrows);
        int4  labn = lab;
        float4 n0 = v0, n1 = v1, n2 = v2, n3 = v3;
        if (haven) {
            labn = *(const int4*)(labels + rn);
            n0 = E4[(size_t)(rn + 0) * D4 + t];
            n1 = E4[(size_t)(rn + 1) * D4 + t];
            n2 = E4[(size_t)(rn + 2) * D4 + t];
            n3 = E4[(size_t)(rn + 3) * D4 + t];
        }
        if (t == 0) {
            atomicAdd(&scnt[lab.x], 1); atomicAdd(&scnt[lab.y], 1);
            atomicAdd(&scnt[lab.z], 1); atomicAdd(&scnt[lab.w], 1);
        }
        float4* p;
        p = &rep[lab.x * D4 + t];
        { float4 a = *p; a.x += v0.x; a.y += v0.y; a.z += v0.z; a.w += v0.w; *p = a; }
        p = &rep[lab.y * D4 + t];
        { float4 a = *p; a.x += v1.x; a.y += v1.y; a.z += v1.z; a.w += v1.w; *p = a; }
        p = &rep[lab.z * D4 + t];
        { float4 a = *p; a.x += v2.x; a.y += v2.y; a.z += v2.z; a.w += v2.w; *p = a; }
        p = &rep[lab.w * D4 + t];
        { float4 a = *p; a.x += v3.x; a.y += v3.y; a.z += v3.z; a.w += v3.w; *p = a; }
        r = rn; have = haven;
        lab = labn; v0 = n0; v1 = n1; v2 = n2; v3 = n3;
    }
    if (r < nrows) {
        for (long rr = r; rr < nrows && rr < r + 4; rr++) {
            int lj = labels[rr];
            float4 v = E4[(size_t)rr * D4 + t];
            if (t == 0) atomicAdd(&scnt[lj], 1);
            float4* p = &rep[lj * D4 + t];
            float4 a = *p; a.x += v.x; a.y += v.y; a.z += v.z; a.w += v.w; *p = a;
        }
    }
    __syncthreads();

    for (int i = threadIdx.x; i < NC * D4; i += 512) {
        float4 a = sm4[i];
        float4 b = sm4[NC * D4 + i];
        float4 c = sm4[2 * NC * D4 + i];
        float4 d = sm4[3 * NC * D4 + i];
        a.x += b.x + c.x + d.x;
        a.y += b.y + c.y + d.y;
        a.z += b.z + c.z + d.z;
        a.w += b.w + c.w + d.w;
        g_part4[blockIdx.x * (NC * D4) + i] = a;
    }
    if (threadIdx.x < NC)
        g_cnt_part[blockIdx.x * NC + threadIdx.x] = scnt[threadIdx.x];
}

// ---------------------------------------------------------------------------
// K2: reduce partials -> PROTOTYPES directly (k_proto folded in).
// Grid 80 x 128. Block b covers f4 elements [16b, 16b+16), all in class b/8
// (128 f4 per class). Each block: (a) reduces its class's count redundantly,
// (b) writes proto = sum * inv, (c) emits its 64-dim ||p||^2 partial to
// g_sqp_part[b]; k_logits sums the 8 partials per class in its prologue.
// Block 0 zeroes g_loss (stream-ordered before k_logits).
// ---------------------------------------------------------------------------
__global__ __launch_bounds__(128) void k_reduce() {
    __shared__ int   scnt_sh;
    __shared__ float ssq[4];
    const int tid = threadIdx.x;
    const int lane = tid & 31;
    const int wid  = tid >> 5;
    const int i  = blockIdx.x * 16 + (tid >> 3);   // f4 element 0..1279
    const int ps = tid & 7;
    const int cls = blockIdx.x >> 3;               // class of all elements here

    if (tid == 0) scnt_sh = 0;
    if (blockIdx.x == 0 && tid == 0) g_loss = 0.f;
    __syncthreads();

    // Class count: redundant per-block reduction over 296 partials.
    int csum = 0;
    for (int p = tid; p < SEG_BLOCKS; p += 128) csum += g_cnt_part[p * NC + cls];
#pragma unroll
    for (int st = 16; st >= 1; st >>= 1) csum += __shfl_xor_sync(0xFFFFFFFFu, csum, st);
    if (lane == 0 && csum) atomicAdd(&scnt_sh, csum);

    // Sum partials for this f4 element (8 threads per element).
    float4 acc = make_float4(0.f, 0.f, 0.f, 0.f);
#pragma unroll 4
    for (int p = ps; p < SEG_BLOCKS; p += 8) {
        float4 v = g_part4[p * (NC * D4) + i];
        acc.x += v.x; acc.y += v.y; acc.z += v.z; acc.w += v.w;
    }
#pragma unroll
    for (int st = 1; st <= 4; st <<= 1) {
        acc.x += __shfl_xor_sync(0xFFFFFFFFu, acc.x, st);
        acc.y += __shfl_xor_sync(0xFFFFFFFFu, acc.y, st);
        acc.z += __shfl_xor_sync(0xFFFFFFFFu, acc.z, st);
        acc.w += __shfl_xor_sync(0xFFFFFFFFu, acc.w, st);
    }

    __syncthreads();                    // scnt_sh final
    const float inv = 1.0f / (float)scnt_sh;

    float4 pr;
    pr.x = acc.x * inv; pr.y = acc.y * inv; pr.z = acc.z * inv; pr.w = acc.w * inv;
    if (ps == 0) g_proto4[i] = pr;

    // ||p||^2 partial for this block (only ps==0 lanes hold valid pr; other
    // lanes contribute garbage confined to unused lanes of the xor tree).
    float s = pr.x * pr.x + pr.y * pr.y + pr.z * pr.z + pr.w * pr.w;
    s += __shfl_xor_sync(0xFFFFFFFFu, s, 8);    // combine lanes 0,8
    s += __shfl_xor_sync(0xFFFFFFFFu, s, 16);   // combine with 16,24
    if (lane == 0) ssq[wid] = s;                // per-warp sum of its 4 elements
    __syncthreads();
    if (tid == 0)
        g_sqp_part[blockIdx.x] = ssq[0] + ssq[1] + ssq[2] + ssq[3];
}

// ---------------------------------------------------------------------------
// K4: logits + log-softmax + loss. R15/R12 kernel FROZEN (measured 82.8us):
// reversed block->row mapping, labels loaded scalar in the epilogue.
// Only prologue change: ssqp[c] = sum of 8 g_sqp_part entries.
// Lane layout per warp: lane = g*8 + ch*4 + dimq; group g owns 4 rows.
// ---------------------------------------------------------------------------
__global__ __launch_bounds__(128, 5) void k_logits(const float4* __restrict__ E4,
                                                   const int* __restrict__ labels,
                                                   float* __restrict__ out,
                                                   int nrows) {
    __shared__ float4 sp[NC * D4];   // 20 KB prototypes
    __shared__ float  ssqp[NC];
    __shared__ float  sloss;

    for (int i = threadIdx.x; i < NC * D4; i += 128) sp[i] = g_proto4[i];
    if (threadIdx.x < NC) {
        float a = 0.f;
#pragma unroll
        for (int b = 0; b < 8; b++) a += g_sqp_part[threadIdx.x * 8 + b];
        ssqp[threadIdx.x] = a;
    }
    if (threadIdx.x == 0) sloss = 0.f;
    __syncthreads();

    const int warp = threadIdx.x >> 5;
    const int lane = threadIdx.x & 31;
    const int dimq = lane & 3;
    const int ch   = (lane >> 2) & 1;
    const int g    = lane >> 3;
    const unsigned gmask = 0xFFu << (g * 8);
    // Reversed mapping: early blocks (scheduled first) take the LAST rows.
    const int rblk = (int)gridDim.x - 1 - (int)blockIdx.x;
    const int r0   = rblk * 64 + warp * 16 + g * 4;

    // Clamped row indices: loads always in-bounds, stores gated by valid.
    int  rowc[4];
    bool valid[4];
#pragma unroll
    for (int j = 0; j < 4; j++) {
        int r = r0 + j;
        valid[j] = (r < nrows);
        rowc[j]  = valid[j] ? r : (nrows - 1);
    }

    const ulonglong2* __restrict__ Pp  = (const ulonglong2*)sp;
    const ulonglong2* __restrict__ Ep0 = (const ulonglong2*)E4 + (size_t)rowc[0] * D4;
    const ulonglong2* __restrict__ Ep1 = (const ulonglong2*)E4 + (size_t)rowc[1] * D4;
    const ulonglong2* __restrict__ Ep2 = (const ulonglong2*)E4 + (size_t)rowc[2] * D4;
    const ulonglong2* __restrict__ Ep3 = (const ulonglong2*)E4 + (size_t)rowc[3] * D4;
    const ulonglong2* __restrict__ Pc  = Pp + (size_t)(ch * 5) * D4;

    ull dot[4][5];
#pragma unroll
    for (int j = 0; j < 4; j++)
#pragma unroll
        for (int c = 0; c < 5; c++) dot[j][c] = 0ull;
    ull sq[4] = {0ull, 0ull, 0ull, 0ull};

#pragma unroll 2
    for (int k = 0; k < 32; k++) {
        const int idx = k * 4 + dimq;
        ulonglong2 v0 = Ep0[idx];
        ulonglong2 v1 = Ep1[idx];
        ulonglong2 v2 = Ep2[idx];
        ulonglong2 v3 = Ep3[idx];
        sq[0] = fma2(v0.x, v0.x, sq[0]); sq[0] = fma2(v0.y, v0.y, sq[0]);
        sq[1] = fma2(v1.x, v1.x, sq[1]); sq[1] = fma2(v1.y, v1.y, sq[1]);
        sq[2] = fma2(v2.x, v2.x, sq[2]); sq[2] = fma2(v2.y, v2.y, sq[2]);
        sq[3] = fma2(v3.x, v3.x, sq[3]); sq[3] = fma2(v3.y, v3.y, sq[3]);
#pragma unroll
        for (int c = 0; c < 5; c++) {
            ulonglong2 p = Pc[c * D4 + idx];
            dot[0][c] = fma2(v0.x, p.x, dot[0][c]); dot[0][c] = fma2(v0.y, p.y, dot[0][c]);
            dot[1][c] = fma2(v1.x, p.x, dot[1][c]); dot[1][c] = fma2(v1.y, p.y, dot[1][c]);
            dot[2][c] = fma2(v2.x, p.x, dot[2][c]); dot[2][c] = fma2(v2.y, p.y, dot[2][c]);
            dot[3][c] = fma2(v3.x, p.x, dot[3][c]); dot[3][c] = fma2(v3.y, p.y, dot[3][c]);
        }
    }

    float lvsum = 0.f;
#pragma unroll
    for (int j = 0; j < 4; j++) {
        float sqe = u64_sum2(sq[j]);
        sqe += __shfl_xor_sync(gmask, sqe, 1);
        sqe += __shfl_xor_sync(gmask, sqe, 2);

        float l[5];
        float m5 = -1e30f;
#pragma unroll
        for (int c = 0; c < 5; c++) {
            float d = u64_sum2(dot[j][c]);
            d += __shfl_xor_sync(gmask, d, 1);
            d += __shfl_xor_sync(gmask, d, 2);
            float d2 = sqe + ssqp[ch * 5 + c] - 2.0f * d;
            float lg = -fmaxf(d2, 0.0f);
            l[c] = lg;
            m5 = fmaxf(m5, lg);
        }
        float m = fmaxf(m5, __shfl_xor_sync(gmask, m5, 4));
        float se5 = 0.f;
#pragma unroll
        for (int c = 0; c < 5; c++) se5 += __expf(l[c] - m);
        float se = se5 + __shfl_xor_sync(gmask, se5, 4);

        const int lab = labels[rowc[j]];
        float lsel5 = 0.f;
#pragma unroll
        for (int c = 0; c < 5; c++)
            if (ch * 5 + c == lab) lsel5 = l[c];
        float lsel = lsel5 + __shfl_xor_sync(gmask, lsel5, 4);

        if (dimq == 0 && valid[j]) {
            float* o = out + 1 + (size_t)rowc[j] * NC + ch * 5;
#pragma unroll
            for (int c = 0; c < 5; c++) o[c] = l[c];
        }
        if (dimq == 0 && ch == 0 && valid[j])
            lvsum += m + __logf(se) - lsel;
    }

#pragma unroll
    for (int st = 16; st >= 1; st >>= 1)
        lvsum += __shfl_xor_sync(0xFFFFFFFFu, lvsum, st);
    if (lane == 0) atomicAdd(&sloss, lvsum);
    __syncthreads();
    if (threadIdx.x == 0) atomicAdd(&g_loss, sloss);
}

// ---------------------------------------------------------------------------
// K5: finalize loss
// ---------------------------------------------------------------------------
__global__ void k_final(float* __restrict__ out, int nrows) {
    out[0] = g_loss * (1.0f / (float)nrows);
}

extern "C" void kernel_launch(void* const* d_in, const int* in_sizes, int n_in,
                              void* d_out, int out_size) {
    const float* E      = (const float*)d_in[0];
    const int*   labels = (const int*)d_in[1];
    float*       out    = (float*)d_out;
    const int nrows = in_sizes[1];   // 131072

    cudaFuncSetAttribute(k_segsum, cudaFuncAttributeMaxDynamicSharedMemorySize,
                         SEG_SMEM);

    k_segsum<<<SEG_BLOCKS, 512, SEG_SMEM>>>((const float4*)E, labels, nrows);
    k_reduce<<<80, 128>>>();
    k_logits<<<(nrows + 63) / 64, 128>>>((const float4*)E, labels, out, nrows);
    k_final<<<1, 1>>>(out, nrows);
}